// round 12
// baseline (speedup 1.0000x reference)
#include <cuda_runtime.h>
#include <math.h>
#include <stdint.h>

// ---------------- static scratch (no allocations allowed) ----------------
#define MAX_GRAPHS 4096
#define MAX_NODES  1048576

__device__ float    d_pre[MAX_GRAPHS * 64];   // per-graph bias: (ga@Wg+bg)@Wn_bot + bn
__device__ float    d_s  [MAX_NODES];         // per-node logits
__device__ uint32_t d_Wfrag[8 * 8 * 32 * 2];  // W b-fragments, tf32(RNA) bits
__device__ int      d_start[MAX_GRAPHS + 1];  // segment starts (d_start[B] = N)

// ---------------- helpers ----------------
__device__ __forceinline__ int detect_i64(const void* nb, int N) {
    int p = (N / 2) | 1;
    return ((const int*)nb)[p] == 0;   // int64 high word == 0; int32 value ~2048 != 0
}
__device__ __forceinline__ int get_seg(const void* nb, int i, int is64) {
    return is64 ? (int)((const long long*)nb)[i] : ((const int*)nb)[i];
}
__device__ __forceinline__ float warp_max(float v) {
    #pragma unroll
    for (int o = 16; o; o >>= 1) v = fmaxf(v, __shfl_xor_sync(0xffffffffu, v, o));
    return v;
}
__device__ __forceinline__ float warp_sum(float v) {
    #pragma unroll
    for (int o = 16; o; o >>= 1) v += __shfl_xor_sync(0xffffffffu, v, o);
    return v;
}
__device__ __forceinline__ uint32_t f2tf32(float f) {
    uint32_t r;
    asm("cvt.rna.tf32.f32 %0, %1;" : "=r"(r) : "f"(f));
    return r;
}
__device__ __forceinline__ float softplus_f(float z) {
    float t = __expf(-fabsf(z));                 // 2 MUFU total
    return fmaxf(z, 0.f) + 0.69314718056f * __log2f(1.f + t);
}
__device__ __forceinline__ uint32_t smem_u32(const void* p) {
    uint32_t a;
    asm("{ .reg .u64 t; cvta.to.shared.u64 t, %1; cvt.u32.u64 %0, t; }" : "=r"(a) : "l"(p));
    return a;
}
__device__ __forceinline__ void cp_async16(uint32_t dst, const void* src, int src_bytes) {
    asm volatile("cp.async.cg.shared.global [%0], [%1], 16, %2;"
                 :: "r"(dst), "l"(src), "r"(src_bytes) : "memory");
}
__device__ __forceinline__ uint32_t lds32(uint32_t a) {
    uint32_t v;
    asm volatile("ld.shared.b32 %0, [%1];" : "=r"(v) : "r"(a));
    return v;
}
// m16n8k8 tf32 mma, D += A*B (C=D in-place). A holds raw fp32 bits (HW truncates).
__device__ __forceinline__ void mma_tf32(float* d, const uint32_t* a, const uint32_t* b) {
    asm volatile(
        "mma.sync.aligned.m16n8k8.row.col.f32.tf32.tf32.f32 "
        "{%0,%1,%2,%3}, {%4,%5,%6,%7}, {%8,%9}, {%0,%1,%2,%3};"
        : "+f"(d[0]), "+f"(d[1]), "+f"(d[2]), "+f"(d[3])
        : "r"(a[0]), "r"(a[1]), "r"(a[2]), "r"(a[3]), "r"(b[0]), "r"(b[1]));
}

// ---------------- kernel 0: fused setup (pre + Wfrag prep + bounds) ----------
// blocks [0, B/4): pre (4 graphs/block); block B/4: Wfrag; blocks > B/4: bounds
__global__ __launch_bounds__(256) void k_setup(
        const float* __restrict__ ga, const float* __restrict__ Wg,
        const float* __restrict__ bg, const float* __restrict__ Wn,
        const float* __restrict__ bn, const void* __restrict__ nb,
        int N, int B) {
    int pb = B >> 2;                 // pre blocks (256 thr = 4 graphs)
    int bid = blockIdx.x;
    if (bid < pb) {
        __shared__ float gsh[4][64];
        int sub = threadIdx.x >> 6, j = threadIdx.x & 63;
        int b = bid * 4 + sub;
        float a0 = ga[b * 3 + 0], a1 = ga[b * 3 + 1], a2 = ga[b * 3 + 2];
        gsh[sub][j] = bg[j] + a0 * Wg[j] + a1 * Wg[64 + j] + a2 * Wg[128 + j];
        __syncthreads();
        float acc = bn[j];
        #pragma unroll 8
        for (int m = 0; m < 64; m++)
            acc += gsh[sub][m] * Wn[(64 + m) * 64 + j];
        d_pre[b * 64 + j] = acc;
    } else if (bid == pb) {
        // b0 = W[kt*8 + (lane&3)][nt*8 + (lane>>2)], b1 same +4 k-rows (RNA tf32)
        #pragma unroll
        for (int it = 0; it < 16; it++) {
            int idx = it * 256 + threadIdx.x;          // 0..4095
            int reg  = idx & 1;
            int lane = (idx >> 1) & 31;
            int nt   = (idx >> 6) & 7;
            int kt   = idx >> 9;
            int krow = kt * 8 + (lane & 3) + reg * 4;
            int col  = nt * 8 + (lane >> 2);
            d_Wfrag[idx] = f2tf32(Wn[krow * 64 + col]);
        }
    } else {
        int i = (bid - pb - 1) * 256 + threadIdx.x;
        if (i >= N) return;
        int is64 = detect_i64(nb, N);
        int cur  = get_seg(nb, i, is64);
        int prev = (i == 0) ? -1 : get_seg(nb, i - 1, is64);
        for (int b = prev + 1; b <= cur; b++) d_start[b] = i;   // empty segments too
        if (i == N - 1)
            for (int b = cur + 1; b <= B; b++) d_start[b] = N;  // tail + sentinel
    }
}

// ---------------- kernel 1: persistent double-buffered tf32 GEMM + epilogue ---
// 128 rows/tile, 4 warps; warp w owns rows [w*32, w*32+32), all 64 cols.
// dyn smem: X stage0 @0 (32KB), X stage1 @32768, Wfrag @65536 (16KB) = 80KB
#define SMEM_BYTES 81920
#define GRID_MMA   296

__global__ void __launch_bounds__(128, 2)
k_mma(const float* __restrict__ x, const void* __restrict__ nb,
      const float* __restrict__ Wa, const float* __restrict__ ba, int N) {
    extern __shared__ char smem[];
    uint32_t sb  = smem_u32(smem);
    uint32_t sWb = sb + 65536;
    const uint32_t* sW = (const uint32_t*)(smem + 65536);

    int tid  = threadIdx.x;
    int wid  = tid >> 5, lane = tid & 31;
    int numTiles = (N + 127) >> 7;
    if ((int)blockIdx.x >= numTiles) return;

    int q = lane >> 2, w4 = (lane & 3) << 2;
    int is64 = detect_i64(nb, N);
    float bav = __ldg(ba);
    int cq = (lane & 3) << 1;
    const float2* wa2 = (const float2*)Wa;

    // W: once per CTA
    {
        const char* src = (const char*)d_Wfrag;
        #pragma unroll
        for (int t = tid; t < 1024; t += 128)
            cp_async16(sWb + t * 16, src + t * 16, 16);
    }
    // first X tile into stage 0
    {
        int base = blockIdx.x * 128;
        #pragma unroll
        for (int t = tid; t < 2048; t += 128) {
            int m = t >> 4, c = t & 15;
            int row = base + m;
            uint32_t dst = sb + (uint32_t)m * 256 + (uint32_t)((c ^ (m & 7)) << 4);
            const float* src = (row < N) ? (x + (size_t)row * 64 + c * 4) : x;
            cp_async16(dst, src, (row < N) ? 16 : 0);
        }
    }
    asm volatile("cp.async.commit_group;" ::: "memory");

    int buf = 0;
    for (int ti = blockIdx.x; ti < numTiles; ti += GRID_MMA) {
        int tn = ti + GRID_MMA;
        if (tn < numTiles) {
            int nbase = tn * 128;
            uint32_t bb = sb + (uint32_t)((buf ^ 1) * 32768);
            #pragma unroll
            for (int t = tid; t < 2048; t += 128) {
                int m = t >> 4, c = t & 15;
                int row = nbase + m;
                uint32_t dst = bb + (uint32_t)m * 256 + (uint32_t)((c ^ (m & 7)) << 4);
                const float* src = (row < N) ? (x + (size_t)row * 64 + c * 4) : x;
                cp_async16(dst, src, (row < N) ? 16 : 0);
            }
            asm volatile("cp.async.commit_group;" ::: "memory");
            asm volatile("cp.async.wait_group 1;" ::: "memory");
        } else {
            asm volatile("cp.async.wait_group 0;" ::: "memory");
        }
        __syncthreads();

        int base = ti * 128;
        uint32_t sAb = sb + (uint32_t)(buf * 32768);

        // ---- mainloop: 2 m-tiles x 8 n-tiles, K=64 in 8 steps ----
        float acc[2][8][4];
        #pragma unroll
        for (int mt = 0; mt < 2; mt++)
            #pragma unroll
            for (int nt = 0; nt < 8; nt++)
                #pragma unroll
                for (int r = 0; r < 4; r++) acc[mt][nt][r] = 0.f;

        #pragma unroll
        for (int kt = 0; kt < 8; kt++) {
            uint32_t pc0 = (uint32_t)(((2 * kt + 0) ^ q) << 4) + w4;
            uint32_t pc1 = (uint32_t)(((2 * kt + 1) ^ q) << 4) + w4;
            uint32_t a[2][4];
            #pragma unroll
            for (int mt = 0; mt < 2; mt++) {
                uint32_t rbase = sAb + (uint32_t)((wid * 32 + mt * 16 + q) * 256);
                a[mt][0] = lds32(rbase + pc0);          // (r,   c)
                a[mt][1] = lds32(rbase + 2048 + pc0);   // (r+8, c)
                a[mt][2] = lds32(rbase + pc1);          // (r,   c+4)
                a[mt][3] = lds32(rbase + 2048 + pc1);   // (r+8, c+4)
            }
            uint32_t b[8][2];
            #pragma unroll
            for (int nt = 0; nt < 8; nt++) {
                uint2 bv = *(const uint2*)&sW[(((kt << 3) + nt) << 6) + (lane << 1)];
                b[nt][0] = bv.x; b[nt][1] = bv.y;
            }
            #pragma unroll
            for (int mt = 0; mt < 2; mt++)
                #pragma unroll
                for (int nt = 0; nt < 8; nt++)
                    mma_tf32(acc[mt][nt], a[mt], b[nt]);
        }

        // ---- fused epilogue ----
        #pragma unroll
        for (int mt = 0; mt < 2; mt++) {
            #pragma unroll
            for (int h = 0; h < 2; h++) {
                int row = base + wid * 32 + mt * 16 + q + 8 * h;
                float part = 0.f;
                if (row < N) {
                    int seg = get_seg(nb, row, is64);
                    const float2* pr = (const float2*)(d_pre + (size_t)seg * 64);
                    #pragma unroll
                    for (int nt = 0; nt < 8; nt++) {
                        int col0 = nt * 8 + cq;
                        float2 p2 = __ldg(pr + (col0 >> 1));
                        float2 w2 = __ldg(wa2 + (col0 >> 1));
                        float z0 = acc[mt][nt][2 * h + 0] + p2.x;
                        float z1 = acc[mt][nt][2 * h + 1] + p2.y;
                        part = fmaf(softplus_f(z0), w2.x, part);
                        part = fmaf(softplus_f(z1), w2.y, part);
                    }
                }
                part += __shfl_xor_sync(0xffffffffu, part, 1);
                part += __shfl_xor_sync(0xffffffffu, part, 2);
                if ((lane & 3) == 0 && row < N) d_s[row] = part + bav;
            }
        }
        __syncthreads();   // done reading this stage before it is refilled
        buf ^= 1;
    }
}

// ---------------- kernel 2: warp-per-segment softmax (bounds precomputed) -----
__global__ __launch_bounds__(256) void k_seg2(float* __restrict__ out, int B) {
    int warp = (blockIdx.x * 256 + threadIdx.x) >> 5;
    int lane = threadIdx.x & 31;
    if (warp >= B) return;
    int s0 = d_start[warp], s1 = d_start[warp + 1];

    float mx = -INFINITY;
    for (int i = s0 + lane; i < s1; i += 32) mx = fmaxf(mx, d_s[i]);
    mx = warp_max(mx);

    float sum = 0.f;
    for (int i = s0 + lane; i < s1; i += 32) sum += __expf(d_s[i] - mx);
    sum = warp_sum(sum);
    float inv = 1.f / (sum + 1e-16f);

    for (int i = s0 + lane; i < s1; i += 32)
        out[i] = __expf(d_s[i] - mx) * inv;
}

// ---------------- launch ----------------
extern "C" void kernel_launch(void* const* d_in, const int* in_sizes, int n_in,
                              void* d_out, int out_size) {
    const float* x  = (const float*)d_in[0];
    const void*  nb = d_in[1];
    const float* ga = (const float*)d_in[2];
    const float* Wg = (const float*)d_in[3];
    const float* bg = (const float*)d_in[4];
    const float* Wn = (const float*)d_in[5];
    const float* bn = (const float*)d_in[6];
    const float* Wa = (const float*)d_in[7];
    const float* ba = (const float*)d_in[8];
    int N = in_sizes[1];
    int B = in_sizes[2] / 3;

    static int cfg_done = 0;
    if (!cfg_done) {
        cudaFuncSetAttribute(k_mma, cudaFuncAttributeMaxDynamicSharedMemorySize, SMEM_BYTES);
        cfg_done = 1;
    }

    int setup_blocks = (B >> 2) + 1 + (N + 255) / 256;
    k_setup<<<setup_blocks, 256>>>(ga, Wg, bg, Wn, bn, nb, N, B);
    k_mma<<<GRID_MMA, 128, SMEM_BYTES>>>(x, nb, Wa, ba, N);
    k_seg2<<<(B * 32 + 255) / 256, 256>>>((float*)d_out, B);
}

// round 13
// speedup vs baseline: 1.2414x; 1.2414x over previous
#include <cuda_runtime.h>
#include <math.h>
#include <stdint.h>

// ---------------- static scratch (no allocations allowed) ----------------
#define MAX_GRAPHS 4096
#define MAX_NODES  1048576

__device__ float    d_pre[MAX_GRAPHS * 64];   // per-graph bias: (ga@Wg+bg)@Wn_bot + bn
__device__ float    d_s  [MAX_NODES];         // per-node logits
__device__ uint32_t d_Wfrag[8 * 8 * 32 * 2];  // W b-fragments, tf32(RNA) bits
__device__ int      d_start[MAX_GRAPHS + 1];  // segment starts (d_start[B] = N)

// ---------------- helpers ----------------
__device__ __forceinline__ int detect_i64(const void* nb, int N) {
    int p = (N / 2) | 1;
    return ((const int*)nb)[p] == 0;   // int64 high word == 0; int32 value ~2048 != 0
}
__device__ __forceinline__ int get_seg(const void* nb, int i, int is64) {
    return is64 ? (int)((const long long*)nb)[i] : ((const int*)nb)[i];
}
__device__ __forceinline__ float warp_max(float v) {
    #pragma unroll
    for (int o = 16; o; o >>= 1) v = fmaxf(v, __shfl_xor_sync(0xffffffffu, v, o));
    return v;
}
__device__ __forceinline__ float warp_sum(float v) {
    #pragma unroll
    for (int o = 16; o; o >>= 1) v += __shfl_xor_sync(0xffffffffu, v, o);
    return v;
}
__device__ __forceinline__ uint32_t f2tf32(float f) {
    uint32_t r;
    asm("cvt.rna.tf32.f32 %0, %1;" : "=r"(r) : "f"(f));
    return r;
}
__device__ __forceinline__ float softplus_f(float z) {
    float t = __expf(-fabsf(z));                 // 2 MUFU total
    return fmaxf(z, 0.f) + 0.69314718056f * __log2f(1.f + t);
}
__device__ __forceinline__ uint32_t smem_u32(const void* p) {
    uint32_t a;
    asm("{ .reg .u64 t; cvta.to.shared.u64 t, %1; cvt.u32.u64 %0, t; }" : "=r"(a) : "l"(p));
    return a;
}
__device__ __forceinline__ void cp_async16(uint32_t dst, const void* src, int src_bytes) {
    asm volatile("cp.async.cg.shared.global [%0], [%1], 16, %2;"
                 :: "r"(dst), "l"(src), "r"(src_bytes) : "memory");
}
__device__ __forceinline__ uint32_t lds32(uint32_t a) {
    uint32_t v;
    asm volatile("ld.shared.b32 %0, [%1];" : "=r"(v) : "r"(a));
    return v;
}
// m16n8k8 tf32 mma, D += A*B (C=D in-place). A holds raw fp32 bits (HW truncates).
__device__ __forceinline__ void mma_tf32(float* d, const uint32_t* a, const uint32_t* b) {
    asm volatile(
        "mma.sync.aligned.m16n8k8.row.col.f32.tf32.tf32.f32 "
        "{%0,%1,%2,%3}, {%4,%5,%6,%7}, {%8,%9}, {%0,%1,%2,%3};"
        : "+f"(d[0]), "+f"(d[1]), "+f"(d[2]), "+f"(d[3])
        : "r"(a[0]), "r"(a[1]), "r"(a[2]), "r"(a[3]), "r"(b[0]), "r"(b[1]));
}

// ---------------- kernel 0: fused setup (pre + Wfrag prep) ----------
// blocks [0, B/4): pre (4 graphs/block); block B/4: Wfrag
__global__ __launch_bounds__(256) void k_setup(
        const float* __restrict__ ga, const float* __restrict__ Wg,
        const float* __restrict__ bg, const float* __restrict__ Wn,
        const float* __restrict__ bn, int B) {
    int pb = B >> 2;                 // pre blocks (256 thr = 4 graphs)
    int bid = blockIdx.x;
    if (bid < pb) {
        __shared__ float gsh[4][64];
        int sub = threadIdx.x >> 6, j = threadIdx.x & 63;
        int b = bid * 4 + sub;
        float a0 = ga[b * 3 + 0], a1 = ga[b * 3 + 1], a2 = ga[b * 3 + 2];
        gsh[sub][j] = bg[j] + a0 * Wg[j] + a1 * Wg[64 + j] + a2 * Wg[128 + j];
        __syncthreads();
        float acc = bn[j];
        #pragma unroll 8
        for (int m = 0; m < 64; m++)
            acc += gsh[sub][m] * Wn[(64 + m) * 64 + j];
        d_pre[b * 64 + j] = acc;
    } else {
        // b0 = W[kt*8 + (lane&3)][nt*8 + (lane>>2)], b1 same +4 k-rows (RNA tf32)
        #pragma unroll
        for (int it = 0; it < 16; it++) {
            int idx = it * 256 + threadIdx.x;          // 0..4095
            int reg  = idx & 1;
            int lane = (idx >> 1) & 31;
            int nt   = (idx >> 6) & 7;
            int kt   = idx >> 9;
            int krow = kt * 8 + (lane & 3) + reg * 4;
            int col  = nt * 8 + (lane >> 2);
            d_Wfrag[idx] = f2tf32(Wn[krow * 64 + col]);
        }
    }
}

// ---------------- kernel 1: tf32 mma.sync GEMM + fused epilogue + bounds ------
// 128 nodes/CTA, 4 warps; warp w owns rows [w*32, w*32+32), all 64 cols.
// sA: row-major fp32 X tile, 16B-chunk XOR swizzle: chunk_phys = chunk_log ^ (row&7).
// sW: b-frags [kt][nt][lane][reg] (tf32 RNA bits). sSeg: prefetched segment ids.
__global__ void __launch_bounds__(128, 4)
k_mma(const float* __restrict__ x, const void* __restrict__ nb,
      const float* __restrict__ Wa, const float* __restrict__ ba, int N, int B) {
    __shared__ float    sA[128 * 64];   // 32 KB
    __shared__ uint32_t sW[8 * 8 * 64]; // 16 KB
    __shared__ int      sSeg[128];

    int tid  = threadIdx.x;
    int wid  = tid >> 5, lane = tid & 31;
    int base = blockIdx.x * 128;
    uint32_t sAb = smem_u32(sA), sWb = smem_u32(sW);
    int is64 = detect_i64(nb, N);

    // async W copy (16 KB, 1024 x 16B)
    {
        const char* src = (const char*)d_Wfrag;
        #pragma unroll
        for (int t = tid; t < 1024; t += 128)
            cp_async16(sWb + t * 16, src + t * 16, 16);
    }
    // async X copy (32 KB) with chunk swizzle; OOB rows zero-filled via src_bytes=0
    {
        #pragma unroll
        for (int t = tid; t < 2048; t += 128) {
            int m = t >> 4, c = t & 15;
            int row = base + m;
            uint32_t dst = sAb + (uint32_t)m * 256 + (uint32_t)((c ^ (m & 7)) << 4);
            const float* src = (row < N) ? (x + (size_t)row * 64 + c * 4) : x;
            cp_async16(dst, src, (row < N) ? 16 : 0);
        }
    }
    asm volatile("cp.async.commit_group;" ::: "memory");

    // segment prefetch + boundary detection (overlaps cp.async drain)
    {
        int i = base + tid;
        if (i < N) {
            int cur  = get_seg(nb, i, is64);
            int prev = (i == 0) ? -1 : get_seg(nb, i - 1, is64);
            sSeg[tid] = cur;
            for (int b = prev + 1; b <= cur; b++) d_start[b] = i;   // empty segs too
            if (i == N - 1)
                for (int b = cur + 1; b <= B; b++) d_start[b] = N;  // tail + sentinel
        } else {
            sSeg[tid] = 0;
        }
    }

    asm volatile("cp.async.wait_group 0;" ::: "memory");
    __syncthreads();

    // ---- mainloop: 2 m-tiles x 8 n-tiles, K=64 in 8 steps ----
    float acc[2][8][4];
    #pragma unroll
    for (int mt = 0; mt < 2; mt++)
        #pragma unroll
        for (int nt = 0; nt < 8; nt++)
            #pragma unroll
            for (int r = 0; r < 4; r++) acc[mt][nt][r] = 0.f;

    int q = lane >> 2, w4 = (lane & 3) << 2;

    #pragma unroll
    for (int kt = 0; kt < 8; kt++) {
        uint32_t pc0 = (uint32_t)(((2 * kt + 0) ^ q) << 4) + w4;
        uint32_t pc1 = (uint32_t)(((2 * kt + 1) ^ q) << 4) + w4;
        uint32_t a[2][4];
        #pragma unroll
        for (int mt = 0; mt < 2; mt++) {
            uint32_t rbase = sAb + (uint32_t)((wid * 32 + mt * 16 + q) * 256);
            a[mt][0] = lds32(rbase + pc0);          // (r,   c)
            a[mt][1] = lds32(rbase + 2048 + pc0);   // (r+8, c)
            a[mt][2] = lds32(rbase + pc1);          // (r,   c+4)
            a[mt][3] = lds32(rbase + 2048 + pc1);   // (r+8, c+4)
        }
        uint32_t b[8][2];
        #pragma unroll
        for (int nt = 0; nt < 8; nt++) {
            uint2 bv = *(const uint2*)&sW[(((kt << 3) + nt) << 6) + (lane << 1)];
            b[nt][0] = bv.x; b[nt][1] = bv.y;
        }
        #pragma unroll
        for (int mt = 0; mt < 2; mt++)
            #pragma unroll
            for (int nt = 0; nt < 8; nt++)
                mma_tf32(acc[mt][nt], a[mt], b[nt]);
    }

    // ---- fused epilogue ----
    float bav = __ldg(ba);
    int cq = (lane & 3) << 1;
    const float2* wa2 = (const float2*)Wa;

    #pragma unroll
    for (int mt = 0; mt < 2; mt++) {
        #pragma unroll
        for (int h = 0; h < 2; h++) {
            int ln  = wid * 32 + mt * 16 + q + 8 * h;
            int row = base + ln;
            float part = 0.f;
            if (row < N) {
                int seg = sSeg[ln];
                const float2* pr = (const float2*)(d_pre + (size_t)seg * 64);
                #pragma unroll
                for (int nt = 0; nt < 8; nt++) {
                    int col0 = nt * 8 + cq;
                    float2 p2 = __ldg(pr + (col0 >> 1));
                    float2 w2 = __ldg(wa2 + (col0 >> 1));
                    float z0 = acc[mt][nt][2 * h + 0] + p2.x;
                    float z1 = acc[mt][nt][2 * h + 1] + p2.y;
                    part = fmaf(softplus_f(z0), w2.x, part);
                    part = fmaf(softplus_f(z1), w2.y, part);
                }
            }
            part += __shfl_xor_sync(0xffffffffu, part, 1);
            part += __shfl_xor_sync(0xffffffffu, part, 2);
            if ((lane & 3) == 0 && row < N) d_s[row] = part + bav;
        }
    }
}

// ---------------- kernel 2: warp-per-segment softmax (bounds precomputed) -----
__global__ __launch_bounds__(256) void k_seg2(float* __restrict__ out, int B) {
    int warp = (blockIdx.x * 256 + threadIdx.x) >> 5;
    int lane = threadIdx.x & 31;
    if (warp >= B) return;
    int s0 = d_start[warp], s1 = d_start[warp + 1];

    float mx = -INFINITY;
    for (int i = s0 + lane; i < s1; i += 32) mx = fmaxf(mx, d_s[i]);
    mx = warp_max(mx);

    float sum = 0.f;
    for (int i = s0 + lane; i < s1; i += 32) sum += __expf(d_s[i] - mx);
    sum = warp_sum(sum);
    float inv = 1.f / (sum + 1e-16f);

    for (int i = s0 + lane; i < s1; i += 32)
        out[i] = __expf(d_s[i] - mx) * inv;
}

// ---------------- launch ----------------
extern "C" void kernel_launch(void* const* d_in, const int* in_sizes, int n_in,
                              void* d_out, int out_size) {
    const float* x  = (const float*)d_in[0];
    const void*  nb = d_in[1];
    const float* ga = (const float*)d_in[2];
    const float* Wg = (const float*)d_in[3];
    const float* bg = (const float*)d_in[4];
    const float* Wn = (const float*)d_in[5];
    const float* bn = (const float*)d_in[6];
    const float* Wa = (const float*)d_in[7];
    const float* ba = (const float*)d_in[8];
    int N = in_sizes[1];
    int B = in_sizes[2] / 3;

    k_setup<<<(B >> 2) + 1, 256>>>(ga, Wg, bg, Wn, bn, B);
    k_mma<<<(N + 127) / 128, 128>>>(x, nb, Wa, ba, N, B);
    k_seg2<<<(B * 32 + 255) / 256, 256>>>((float*)d_out, B);
}